// round 4
// baseline (speedup 1.0000x reference)
#include <cuda_runtime.h>
#include <cuda_bf16.h>
#include <math.h>

// ---------------------------------------------------------------------------
// SphereDistanceField: Instant-NGP hash-grid encode (16 levels, F=2) + MLP
// 35 -> 64 -> 64 -> 1, softplus(out + 1).
// One thread per ray. Weights in shared; activations staged in shared per
// thread (conflict-free column layout). MLP math uses packed fma.rn.f32x2
// (2x fp32 MAC rate on sm_103a).
// ---------------------------------------------------------------------------

#define NLEV 16
#define TSIZE (1u << 19)
#define TMASK (TSIZE - 1u)
#define PRIME1 2654435761u
#define PRIME2 805459861u

#define BLOCK 256

// shared layout (floats)
#define W1_OFF 0        // 35*64 = 2240
#define B1_OFF 2240     // 64
#define W2_OFF 2304     // 64*64 = 4096
#define B2_OFF 6400     // 64
#define W3_OFF 6464     // 64
#define B3_OFF 6528     // 1
#define WTOT   6529
#define H_OFF  6544     // 16B aligned (6544*4 = 26176); hstage: 64 rows x BLOCK
#define SMEM_FLOATS (H_OFF + 64 * BLOCK)
#define SMEM_BYTES  (SMEM_FLOATS * 4)

struct Scales { float s[NLEV]; };

typedef unsigned long long u64t;

__device__ __forceinline__ u64t ffma2(u64t a, u64t b, u64t c) {
    u64t d;
    asm("fma.rn.f32x2 %0, %1, %2, %3;" : "=l"(d) : "l"(a), "l"(b), "l"(c));
    return d;
}
__device__ __forceinline__ u64t pack2(float v) {
    u64t r; unsigned u = __float_as_uint(v);
    asm("mov.b64 %0, {%1, %1};" : "=l"(r) : "r"(u));
    return r;
}
__device__ __forceinline__ void unpack2(u64t p, float& lo, float& hi) {
    unsigned a, b;
    asm("mov.b64 {%0, %1}, %2;" : "=r"(a), "=r"(b) : "l"(p));
    lo = __uint_as_float(a); hi = __uint_as_float(b);
}

__global__ __launch_bounds__(BLOCK, 2)
void sdf_kernel(const float* __restrict__ dirs,
                const float* __restrict__ table,
                const float* __restrict__ W1, const float* __restrict__ b1,
                const float* __restrict__ W2, const float* __restrict__ b2,
                const float* __restrict__ W3, const float* __restrict__ b3,
                float* __restrict__ out, int n, Scales sc)
{
    extern __shared__ __align__(16) float smem[];
    const int tid = threadIdx.x;

    // ---- cooperative weight load into shared ----
    for (int i = tid; i < WTOT; i += BLOCK) {
        float v;
        if      (i < B1_OFF) v = W1[i];
        else if (i < W2_OFF) v = b1[i - B1_OFF];
        else if (i < B2_OFF) v = W2[i - W2_OFF];
        else if (i < W3_OFF) v = b2[i - B2_OFF];
        else if (i < B3_OFF) v = W3[i - W3_OFF];
        else                 v = b3[0];
        smem[i] = v;
    }
    __syncthreads();

    const int ray = blockIdx.x * BLOCK + tid;
    if (ray >= n) return;

    float* hcol = smem + H_OFF + tid;   // per-thread activation column, stride BLOCK

    // ---- load direction, map to [0,1] cube ----
    const float dx = dirs[ray * 3 + 0];
    const float dy = dirs[ray * 3 + 1];
    const float dz = dirs[ray * 3 + 2];
    const float x = fmaf(dx, 0.49f, 0.49f);
    const float y = fmaf(dy, 0.49f, 0.49f);
    const float z = fmaf(dz, 0.49f, 0.49f);

    hcol[0 * BLOCK] = dx;
    hcol[1 * BLOCK] = dy;
    hcol[2 * BLOCK] = dz;

    // ---- hash grid encode ----
    // dense levels 0..4 (res^3 <= 2^19), hashed levels 5..15
    const unsigned RES[5] = {16u, 23u, 31u, 43u, 59u};

    #pragma unroll
    for (int l = 0; l < NLEV; l++) {
        const float s = sc.s[l];
        const float px = fmaf(x, s, 0.5f);
        const float py = fmaf(y, s, 0.5f);
        const float pz = fmaf(z, s, 0.5f);
        const float fpx = floorf(px), fpy = floorf(py), fpz = floorf(pz);
        const float fx = px - fpx, fy = py - fpy, fz = pz - fpz;
        const unsigned ix = (unsigned)fpx, iy = (unsigned)fpy, iz = (unsigned)fpz;
        // smoothstep weights
        const float wx = fx * fx * (3.0f - 2.0f * fx);
        const float wy = fy * fy * (3.0f - 2.0f * fy);
        const float wz = fz * fz * (3.0f - 2.0f * fz);
        const float wx0 = 1.0f - wx, wy0 = 1.0f - wy, wz0 = 1.0f - wz;

        unsigned idx0, idx1, idx2, idx3, idx4, idx5, idx6, idx7;
        if (l < 5) {
            const unsigned R = RES[l], R2 = R * R;
            const unsigned base = ix + iy * R + iz * R2;
            idx0 = base;            idx1 = base + 1u;
            idx2 = base + R;        idx3 = base + R + 1u;
            idx4 = base + R2;       idx5 = base + R2 + 1u;
            idx6 = base + R2 + R;   idx7 = base + R2 + R + 1u;
        } else {
            const unsigned hx0 = ix,          hx1 = ix + 1u;
            const unsigned hy0 = iy * PRIME1, hy1 = hy0 + PRIME1;
            const unsigned hz0 = iz * PRIME2, hz1 = hz0 + PRIME2;
            idx0 = (hx0 ^ hy0 ^ hz0) & TMASK;  idx1 = (hx1 ^ hy0 ^ hz0) & TMASK;
            idx2 = (hx0 ^ hy1 ^ hz0) & TMASK;  idx3 = (hx1 ^ hy1 ^ hz0) & TMASK;
            idx4 = (hx0 ^ hy0 ^ hz1) & TMASK;  idx5 = (hx1 ^ hy0 ^ hz1) & TMASK;
            idx6 = (hx0 ^ hy1 ^ hz1) & TMASK;  idx7 = (hx1 ^ hy1 ^ hz1) & TMASK;
        }

        const float2* tl = reinterpret_cast<const float2*>(table) + (size_t)l * TSIZE;
        const float2 c0 = tl[idx0], c1 = tl[idx1], c2 = tl[idx2], c3 = tl[idx3];
        const float2 c4 = tl[idx4], c5 = tl[idx5], c6 = tl[idx6], c7 = tl[idx7];

        const float w00 = wx0 * wy0, w10 = wx * wy0;
        const float w01 = wx0 * wy,  w11 = wx * wy;

        float t0 = c0.x * w00;  t0 = fmaf(c1.x, w10, t0);
        t0 = fmaf(c2.x, w01, t0); t0 = fmaf(c3.x, w11, t0);
        float t1 = c4.x * w00;  t1 = fmaf(c5.x, w10, t1);
        t1 = fmaf(c6.x, w01, t1); t1 = fmaf(c7.x, w11, t1);
        const float a0 = fmaf(t1, wz, t0 * wz0);

        float u0 = c0.y * w00;  u0 = fmaf(c1.y, w10, u0);
        u0 = fmaf(c2.y, w01, u0); u0 = fmaf(c3.y, w11, u0);
        float u1 = c4.y * w00;  u1 = fmaf(c5.y, w10, u1);
        u1 = fmaf(c6.y, w01, u1); u1 = fmaf(c7.y, w11, u1);
        const float a1 = fmaf(u1, wz, u0 * wz0);

        hcol[(3 + 2 * l) * BLOCK] = a0;
        hcol[(4 + 2 * l) * BLOCK] = a1;
    }

    // ---- MLP layer 1: 35 -> 64 (packed f32x2, 64 accumulators in 32 u64) ----
    u64t acc[32];
    {
        const u64t* bp = reinterpret_cast<const u64t*>(smem + B1_OFF);
        #pragma unroll
        for (int j = 0; j < 32; j++) acc[j] = bp[j];
    }
    #pragma unroll 5
    for (int i = 0; i < 35; i++) {
        const u64t hp = pack2(hcol[i * BLOCK]);
        const ulonglong2* row = reinterpret_cast<const ulonglong2*>(smem + W1_OFF + i * 64);
        #pragma unroll
        for (int j = 0; j < 16; j++) {
            const ulonglong2 w = row[j];
            acc[2 * j]     = ffma2(hp, w.x, acc[2 * j]);
            acc[2 * j + 1] = ffma2(hp, w.y, acc[2 * j + 1]);
        }
    }
    // relu, stage o1 to shared (per-thread column, no sync needed)
    #pragma unroll
    for (int j = 0; j < 32; j++) {
        float lo, hi; unpack2(acc[j], lo, hi);
        hcol[(2 * j) * BLOCK]     = fmaxf(lo, 0.0f);
        hcol[(2 * j + 1) * BLOCK] = fmaxf(hi, 0.0f);
    }

    // ---- MLP layer 2: 64 -> 64 ----
    {
        const u64t* bp = reinterpret_cast<const u64t*>(smem + B2_OFF);
        #pragma unroll
        for (int j = 0; j < 32; j++) acc[j] = bp[j];
    }
    #pragma unroll 4
    for (int i = 0; i < 64; i++) {
        const u64t hp = pack2(hcol[i * BLOCK]);
        const ulonglong2* row = reinterpret_cast<const ulonglong2*>(smem + W2_OFF + i * 64);
        #pragma unroll
        for (int j = 0; j < 16; j++) {
            const ulonglong2 w = row[j];
            acc[2 * j]     = ffma2(hp, w.x, acc[2 * j]);
            acc[2 * j + 1] = ffma2(hp, w.y, acc[2 * j + 1]);
        }
    }

    // ---- layer 3: 64 -> 1 (relu fused), softplus(out + 1) ----
    float outv = smem[B3_OFF];
    #pragma unroll
    for (int j = 0; j < 32; j++) {
        float lo, hi; unpack2(acc[j], lo, hi);
        outv = fmaf(fmaxf(lo, 0.0f), smem[W3_OFF + 2 * j],     outv);
        outv = fmaf(fmaxf(hi, 0.0f), smem[W3_OFF + 2 * j + 1], outv);
    }
    const float xv = outv + 1.0f;
    out[ray] = fmaxf(xv, 0.0f) + log1pf(expf(-fabsf(xv)));
}

extern "C" void kernel_launch(void* const* d_in, const int* in_sizes, int n_in,
                              void* d_out, int out_size) {
    const float* dirs  = (const float*)d_in[0];
    const float* table = (const float*)d_in[1];
    const float* W1 = (const float*)d_in[2];
    const float* b1 = (const float*)d_in[3];
    const float* W2 = (const float*)d_in[4];
    const float* b2 = (const float*)d_in[5];
    const float* W3 = (const float*)d_in[6];
    const float* b3 = (const float*)d_in[7];
    float* out = (float*)d_out;

    const int n = in_sizes[0] / 3;

    // per-level scales computed in double, matching numpy:
    // PLS = exp(log(2048/16)/15); scale_l = 16*PLS^l - 1 (cast to f32)
    Scales sc;
    const double PLS = exp(log(2048.0 / 16.0) / 15.0);
    for (int l = 0; l < NLEV; l++)
        sc.s[l] = (float)(16.0 * pow(PLS, (double)l) - 1.0);

    cudaFuncSetAttribute(sdf_kernel, cudaFuncAttributeMaxDynamicSharedMemorySize,
                         SMEM_BYTES);

    const int blocks = (n + BLOCK - 1) / BLOCK;
    sdf_kernel<<<blocks, BLOCK, SMEM_BYTES>>>(dirs, table, W1, b1, W2, b2, W3, b3,
                                              out, n, sc);
}

// round 6
// speedup vs baseline: 1.3808x; 1.3808x over previous
#include <cuda_runtime.h>
#include <cuda_fp16.h>
#include <math.h>

// ---------------------------------------------------------------------------
// SphereDistanceField: hash-grid encode (fp32) + fully-fused HMMA MLP.
// One thread per ray for the encode; one warp per 32 rays for the MLP
// (m16n8k16 fp16 mma, fp32 accumulate). Weights staged once per block in
// shared (fp16, transposed, stride-72 halves => conflict-free frag loads).
// Layer3 (64->1) fused into layer2 epilogue via quad shfl reduction.
// ---------------------------------------------------------------------------

#define NLEV 16
#define TSIZE (1u << 19)
#define TMASK (TSIZE - 1u)
#define PRIME1 2654435761u
#define PRIME2 805459861u

#define BLOCK 256

// shared layout (bytes)
#define WS1_OFF 0                      // W1^T fp16 [64][72]   = 9216 B
#define WS2_OFF 9216                   // W2^T fp16 [64][72]   = 9216 B
#define B1S_OFF 18432                  // b1 fp32 [64]         = 256 B
#define B2S_OFF (B1S_OFF + 256)        // b2 fp32 [64]
#define W3S_OFF (B2S_OFF + 256)        // W3 fp32 [64]
#define B3S_OFF (W3S_OFF + 256)        // b3 fp32 [1]
#define X_OFF   19456                  // X  fp16 [256][72]    = 36864 B
#define H1_OFF  (X_OFF + 36864)        // H1 fp16 [256][72]    = 36864 B
#define SMEM_BYTES (H1_OFF + 36864)    // 93184 B -> 2 CTAs/SM

struct Scales { float s[NLEV]; };

__device__ __forceinline__ void mma16816(float& c0, float& c1, float& c2, float& c3,
                                         unsigned a0, unsigned a1, unsigned a2, unsigned a3,
                                         unsigned b0, unsigned b1) {
    asm volatile("mma.sync.aligned.m16n8k16.row.col.f32.f16.f16.f32 "
                 "{%0,%1,%2,%3}, {%4,%5,%6,%7}, {%8,%9}, {%0,%1,%2,%3};"
                 : "+f"(c0), "+f"(c1), "+f"(c2), "+f"(c3)
                 : "r"(a0), "r"(a1), "r"(a2), "r"(a3), "r"(b0), "r"(b1));
}

__global__ __launch_bounds__(BLOCK, 2)
void sdf_kernel(const float* __restrict__ dirs,
                const float* __restrict__ table,
                const float* __restrict__ W1, const float* __restrict__ b1,
                const float* __restrict__ W2, const float* __restrict__ b2,
                const float* __restrict__ W3, const float* __restrict__ b3,
                float* __restrict__ out, int n, Scales sc)
{
    extern __shared__ __align__(16) char smem[];
    __half*  ws1h = (__half*)(smem + WS1_OFF);
    __half*  ws2h = (__half*)(smem + WS2_OFF);
    float*   b1s  = (float*)(smem + B1S_OFF);
    float*   b2s  = (float*)(smem + B2S_OFF);
    float*   w3s  = (float*)(smem + W3S_OFF);
    float*   b3s  = (float*)(smem + B3S_OFF);

    const int tid = threadIdx.x;

    // ---- stage weights (transposed, fp16) ----
    // zero W1^T rows (pads cols 35..47 which the K=48 GEMM reads)
    for (int i = tid; i < 64 * 72 / 2; i += BLOCK)
        ((unsigned*)ws1h)[i] = 0u;
    __syncthreads();   // zero before scattered fill (avoid rmw races on halves)
    for (int i = tid; i < 35 * 64; i += BLOCK) {
        int k = i >> 6, nn = i & 63;
        ws1h[nn * 72 + k] = __float2half(W1[i]);
    }
    for (int i = tid; i < 64 * 64; i += BLOCK) {
        int k = i >> 6, nn = i & 63;
        ws2h[nn * 72 + k] = __float2half(W2[i]);
    }
    if (tid < 64) {
        b1s[tid] = b1[tid];
        b2s[tid] = b2[tid];
        w3s[tid] = W3[tid];
        if (tid == 0) b3s[0] = b3[0];
    }
    __syncthreads();

    // ---- encode (one thread = one ray) ----
    const int ray  = blockIdx.x * BLOCK + tid;
    const int rayc = ray < n ? ray : (n - 1);

    const float dx = dirs[rayc * 3 + 0];
    const float dy = dirs[rayc * 3 + 1];
    const float dz = dirs[rayc * 3 + 2];
    const float x = fmaf(dx, 0.49f, 0.49f);
    const float y = fmaf(dy, 0.49f, 0.49f);
    const float z = fmaf(dz, 0.49f, 0.49f);

    __half2* Xh2 = (__half2*)(smem + X_OFF);
    const int xrow = tid * 36;                     // row stride = 72 halves = 36 half2

    Xh2[xrow + 0] = __floats2half2_rn(dx, dy);
    float prev = dz;

    const unsigned RES[5] = {16u, 23u, 31u, 43u, 59u};

    #pragma unroll
    for (int l = 0; l < NLEV; l++) {
        const float s = sc.s[l];
        const float px = fmaf(x, s, 0.5f);
        const float py = fmaf(y, s, 0.5f);
        const float pz = fmaf(z, s, 0.5f);
        const float fpx = floorf(px), fpy = floorf(py), fpz = floorf(pz);
        const float fx = px - fpx, fy = py - fpy, fz = pz - fpz;
        const unsigned ix = (unsigned)fpx, iy = (unsigned)fpy, iz = (unsigned)fpz;
        const float wx = fx * fx * (3.0f - 2.0f * fx);
        const float wy = fy * fy * (3.0f - 2.0f * fy);
        const float wz = fz * fz * (3.0f - 2.0f * fz);
        const float wx0 = 1.0f - wx, wy0 = 1.0f - wy, wz0 = 1.0f - wz;

        unsigned idx0, idx1, idx2, idx3, idx4, idx5, idx6, idx7;
        if (l < 5) {
            const unsigned R = RES[l], R2 = R * R;
            const unsigned base = ix + iy * R + iz * R2;
            idx0 = base;            idx1 = base + 1u;
            idx2 = base + R;        idx3 = base + R + 1u;
            idx4 = base + R2;       idx5 = base + R2 + 1u;
            idx6 = base + R2 + R;   idx7 = base + R2 + R + 1u;
        } else {
            const unsigned hx0 = ix,          hx1 = ix + 1u;
            const unsigned hy0 = iy * PRIME1, hy1 = hy0 + PRIME1;
            const unsigned hz0 = iz * PRIME2, hz1 = hz0 + PRIME2;
            idx0 = (hx0 ^ hy0 ^ hz0) & TMASK;  idx1 = (hx1 ^ hy0 ^ hz0) & TMASK;
            idx2 = (hx0 ^ hy1 ^ hz0) & TMASK;  idx3 = (hx1 ^ hy1 ^ hz0) & TMASK;
            idx4 = (hx0 ^ hy0 ^ hz1) & TMASK;  idx5 = (hx1 ^ hy0 ^ hz1) & TMASK;
            idx6 = (hx0 ^ hy1 ^ hz1) & TMASK;  idx7 = (hx1 ^ hy1 ^ hz1) & TMASK;
        }

        const float2* tl = reinterpret_cast<const float2*>(table) + (size_t)l * TSIZE;
        const float2 c0 = tl[idx0], c1 = tl[idx1], c2 = tl[idx2], c3 = tl[idx3];
        const float2 c4 = tl[idx4], c5 = tl[idx5], c6 = tl[idx6], c7 = tl[idx7];

        const float w00 = wx0 * wy0, w10 = wx * wy0;
        const float w01 = wx0 * wy,  w11 = wx * wy;

        float t0 = c0.x * w00;  t0 = fmaf(c1.x, w10, t0);
        t0 = fmaf(c2.x, w01, t0); t0 = fmaf(c3.x, w11, t0);
        float t1 = c4.x * w00;  t1 = fmaf(c5.x, w10, t1);
        t1 = fmaf(c6.x, w01, t1); t1 = fmaf(c7.x, w11, t1);
        const float a0 = fmaf(t1, wz, t0 * wz0);

        float u0 = c0.y * w00;  u0 = fmaf(c1.y, w10, u0);
        u0 = fmaf(c2.y, w01, u0); u0 = fmaf(c3.y, w11, u0);
        float u1 = c4.y * w00;  u1 = fmaf(c5.y, w10, u1);
        u1 = fmaf(c6.y, w01, u1); u1 = fmaf(c7.y, w11, u1);
        const float a1 = fmaf(u1, wz, u0 * wz0);

        Xh2[xrow + l + 1] = __floats2half2_rn(prev, a0);
        prev = a1;
    }
    Xh2[xrow + 17] = __floats2half2_rn(prev, 0.0f);
    const __half2 zero2 = __floats2half2_rn(0.0f, 0.0f);
    #pragma unroll
    for (int p = 18; p < 24; p++) Xh2[xrow + p] = zero2;

    __syncwarp();

    // ---- fused MLP: one warp = 32 rays ----
    const int lane = tid & 31;
    const int warp = tid >> 5;
    const int g   = lane >> 2;     // 0..7
    const int tig = lane & 3;      // 0..3
    const int wbase = warp * 32;   // warp's row base in X / H1

    const unsigned* Xu  = (const unsigned*)(smem + X_OFF);
    const unsigned* W1u = (const unsigned*)ws1h;
    const unsigned* W2u = (const unsigned*)ws2h;
    __half2*        H1h = (__half2*)(smem + H1_OFF);
    const unsigned* H1u = (const unsigned*)H1h;

    // ---- layer 1: [32,48] @ [48,64] ----
    #pragma unroll
    for (int mt = 0; mt < 2; mt++) {
        const int r0 = wbase + mt * 16 + g;
        unsigned a[3][4];
        #pragma unroll
        for (int kt = 0; kt < 3; kt++) {
            const int o = r0 * 36 + kt * 8 + tig;
            a[kt][0] = Xu[o];           a[kt][1] = Xu[o + 288];
            a[kt][2] = Xu[o + 4];       a[kt][3] = Xu[o + 292];
        }
        #pragma unroll
        for (int nt = 0; nt < 8; nt++) {
            float c0 = 0.f, c1 = 0.f, c2 = 0.f, c3 = 0.f;
            #pragma unroll
            for (int kt = 0; kt < 3; kt++) {
                const int bo = (nt * 8 + g) * 36 + kt * 8 + tig;
                mma16816(c0, c1, c2, c3, a[kt][0], a[kt][1], a[kt][2], a[kt][3],
                         W1u[bo], W1u[bo + 4]);
            }
            const float2 bb = *(const float2*)&b1s[nt * 8 + tig * 2];
            const int ho = r0 * 36 + nt * 4 + tig;
            H1h[ho]       = __floats2half2_rn(fmaxf(c0 + bb.x, 0.f), fmaxf(c1 + bb.y, 0.f));
            H1h[ho + 288] = __floats2half2_rn(fmaxf(c2 + bb.x, 0.f), fmaxf(c3 + bb.y, 0.f));
        }
    }
    __syncwarp();

    // ---- layer 2 + fused layer 3 ----
    const float b3v = b3s[0];
    #pragma unroll
    for (int mt = 0; mt < 2; mt++) {
        const int r0 = wbase + mt * 16 + g;
        unsigned a[4][4];
        #pragma unroll
        for (int kt = 0; kt < 4; kt++) {
            const int o = r0 * 36 + kt * 8 + tig;
            a[kt][0] = H1u[o];          a[kt][1] = H1u[o + 288];
            a[kt][2] = H1u[o + 4];      a[kt][3] = H1u[o + 292];
        }
        float p0 = 0.f, p1 = 0.f;
        #pragma unroll
        for (int nt = 0; nt < 8; nt++) {
            float c0 = 0.f, c1 = 0.f, c2 = 0.f, c3 = 0.f;
            #pragma unroll
            for (int kt = 0; kt < 4; kt++) {
                const int bo = (nt * 8 + g) * 36 + kt * 8 + tig;
                mma16816(c0, c1, c2, c3, a[kt][0], a[kt][1], a[kt][2], a[kt][3],
                         W2u[bo], W2u[bo + 4]);
            }
            const float2 bb  = *(const float2*)&b2s[nt * 8 + tig * 2];
            const float2 w3v = *(const float2*)&w3s[nt * 8 + tig * 2];
            p0 = fmaf(fmaxf(c0 + bb.x, 0.f), w3v.x, p0);
            p0 = fmaf(fmaxf(c1 + bb.y, 0.f), w3v.y, p0);
            p1 = fmaf(fmaxf(c2 + bb.x, 0.f), w3v.x, p1);
            p1 = fmaf(fmaxf(c3 + bb.y, 0.f), w3v.y, p1);
        }
        // reduce across the quad (lanes sharing g)
        p0 += __shfl_xor_sync(0xFFFFFFFFu, p0, 1);
        p0 += __shfl_xor_sync(0xFFFFFFFFu, p0, 2);
        p1 += __shfl_xor_sync(0xFFFFFFFFu, p1, 1);
        p1 += __shfl_xor_sync(0xFFFFFFFFu, p1, 2);

        if (tig == 0) {
            const int rbase = blockIdx.x * BLOCK + wbase + mt * 16 + g;
            {
                const float xv = p0 + b3v + 1.0f;
                if (rbase < n)
                    out[rbase] = fmaxf(xv, 0.0f) + log1pf(expf(-fabsf(xv)));
            }
            {
                const float xv = p1 + b3v + 1.0f;
                if (rbase + 8 < n)
                    out[rbase + 8] = fmaxf(xv, 0.0f) + log1pf(expf(-fabsf(xv)));
            }
        }
    }
}

extern "C" void kernel_launch(void* const* d_in, const int* in_sizes, int n_in,
                              void* d_out, int out_size) {
    const float* dirs  = (const float*)d_in[0];
    const float* table = (const float*)d_in[1];
    const float* W1 = (const float*)d_in[2];
    const float* b1 = (const float*)d_in[3];
    const float* W2 = (const float*)d_in[4];
    const float* b2 = (const float*)d_in[5];
    const float* W3 = (const float*)d_in[6];
    const float* b3 = (const float*)d_in[7];
    float* out = (float*)d_out;

    const int n = in_sizes[0] / 3;

    Scales sc;
    const double PLS = exp(log(2048.0 / 16.0) / 15.0);
    for (int l = 0; l < NLEV; l++)
        sc.s[l] = (float)(16.0 * pow(PLS, (double)l) - 1.0);

    cudaFuncSetAttribute(sdf_kernel, cudaFuncAttributeMaxDynamicSharedMemorySize,
                         SMEM_BYTES);

    const int blocks = (n + BLOCK - 1) / BLOCK;
    sdf_kernel<<<blocks, BLOCK, SMEM_BYTES>>>(dirs, table, W1, b1, W2, b2, W3, b3,
                                              out, n, sc);
}